// round 2
// baseline (speedup 1.0000x reference)
#include <cuda_runtime.h>
#include <math.h>

#define NN 131072
#define NE 2097152
#define NT (NE + NN)   // 2228224 edges incl self loops
#define NG 512

// ---------------- scratch (device globals; no runtime allocation) ----------------
__device__ float  g_xl[NN * 128];
__device__ float  g_xr[NN * 128];
__device__ float  g_deg[NN];
__device__ float  g_loop[NN * 3];
__device__ float  g_maxlog[NN * 2];
__device__ float  g_sum[NN * 2];
__device__ float  g_w[(size_t)NT * 2];
__device__ float  g_agg[NN * 64];
__device__ float  g_h[NN * 64];
__device__ float  g_pool[NG * 64];
__device__ float  g_pcnt[NG];
__device__ float  g_z[NG * 32];
__device__ double g_bns[128];   // [0..C) sum, [C..2C) sumsq
__device__ double g_bns3[64];   // head BN: [0..32) sum, [32..64) sumsq

// ---------------- helpers ----------------
__device__ __forceinline__ void atomicMaxF(float* addr, float v) {
    int* ai = (int*)addr;
    int old = *ai;
    while (__int_as_float(old) < v) {
        int prev = atomicCAS(ai, old, __float_as_int(v));
        if (prev == old) break;
        old = prev;
    }
}

__global__ void k_fill(float* p, float v, int n) {
    int i = blockIdx.x * blockDim.x + threadIdx.x;
    if (i < n) p[i] = v;
}

// ---------------- self-loop attr (mean of incoming edge attrs) ----------------
__global__ void k_deg(const int* __restrict__ ei, const float* __restrict__ ea,
                      float* deg, float* loop) {
    int e = blockIdx.x * blockDim.x + threadIdx.x;
    if (e >= NE) return;
    int dst = ei[NE + e];
    atomicAdd(&deg[dst], 1.0f);
    atomicAdd(&loop[dst * 3 + 0], ea[e * 3 + 0]);
    atomicAdd(&loop[dst * 3 + 1], ea[e * 3 + 1]);
    atomicAdd(&loop[dst * 3 + 2], ea[e * 3 + 2]);
}

__global__ void k_loopfin(float* loop, const float* __restrict__ deg) {
    int n = blockIdx.x * blockDim.x + threadIdx.x;
    if (n >= NN) return;
    float inv = 1.0f / fmaxf(deg[n], 1.0f);
    loop[n * 3 + 0] *= inv;
    loop[n * 3 + 1] *= inv;
    loop[n * 3 + 2] *= inv;
}

// ---------------- node linear: xl = in@wl+bl, xr = in@wr+br ----------------
template <int INW, int OUTW>
__global__ void k_lin(const float* __restrict__ in,
                      const float* __restrict__ wl, const float* __restrict__ bl,
                      const float* __restrict__ wr, const float* __restrict__ br,
                      float* __restrict__ xl, float* __restrict__ xr) {
    __shared__ float sw[2 * INW * OUTW];
    __shared__ float sb[2 * OUTW];
    __shared__ float sx[INW];
    for (int i = threadIdx.x; i < INW * OUTW; i += blockDim.x) {
        sw[i] = wl[i];
        sw[INW * OUTW + i] = wr[i];
    }
    for (int i = threadIdx.x; i < OUTW; i += blockDim.x) {
        sb[i] = bl[i];
        sb[OUTW + i] = br[i];
    }
    __syncthreads();
    for (int n = blockIdx.x; n < NN; n += gridDim.x) {
        __syncthreads();
        for (int i = threadIdx.x; i < INW; i += blockDim.x) sx[i] = in[(size_t)n * INW + i];
        __syncthreads();
        for (int o = threadIdx.x; o < 2 * OUTW; o += blockDim.x) {
            int mat = (o < OUTW) ? 0 : 1;
            int c = mat ? (o - OUTW) : o;
            const float* w = &sw[mat * INW * OUTW];
            float acc = sb[mat * OUTW + c];
            #pragma unroll
            for (int k = 0; k < INW; k++) acc += sx[k] * w[k * OUTW + c];
            (mat ? xr : xl)[(size_t)n * OUTW + c] = acc;
        }
    }
}

// ---------------- pass A: logits + segment max (warp per edge) ----------------
template <int C>
__global__ void k_passA(const int* __restrict__ ei, const float* __restrict__ ea,
                        const float* __restrict__ loop,
                        const float* __restrict__ xl, const float* __restrict__ xr,
                        const float* __restrict__ we, const float* __restrict__ att,
                        float* elog, float* maxlog) {
    const int HC = 2 * C;
    int warp = (blockIdx.x * blockDim.x + threadIdx.x) >> 5;
    int lane = threadIdx.x & 31;
    if (warp >= NT) return;
    int src, dst;
    float av;
    if (warp < NE) {
        src = ei[warp];
        dst = ei[NE + warp];
        av = (lane < 3) ? ea[(size_t)warp * 3 + lane] : 0.0f;
    } else {
        src = dst = warp - NE;
        av = (lane < 3) ? loop[(size_t)src * 3 + lane] : 0.0f;
    }
    float a0 = __shfl_sync(0xFFFFFFFFu, av, 0);
    float a1 = __shfl_sync(0xFFFFFFFFu, av, 1);
    float a2 = __shfl_sync(0xFFFFFFFFu, av, 2);

    const float* xls = xl + (size_t)src * HC;
    const float* xrd = xr + (size_t)dst * HC;
    float l0 = 0.0f, l1 = 0.0f;
    #pragma unroll
    for (int j = 0; j < HC / 32; j++) {
        int col = lane + j * 32;
        float eev = a0 * we[col] + a1 * we[HC + col] + a2 * we[2 * HC + col];
        float m = xls[col] + xrd[col] + eev;
        m = (m > 0.0f) ? m : 0.2f * m;       // leaky_relu 0.2
        float contrib = m * att[col];        // att[h*C+c] == att[col]
        if (col < C) l0 += contrib; else l1 += contrib;
    }
    #pragma unroll
    for (int off = 16; off; off >>= 1) {
        l0 += __shfl_xor_sync(0xFFFFFFFFu, l0, off);
        l1 += __shfl_xor_sync(0xFFFFFFFFu, l1, off);
    }
    if (lane == 0) {
        elog[(size_t)warp * 2 + 0] = l0;
        elog[(size_t)warp * 2 + 1] = l1;
        atomicMaxF(&maxlog[dst * 2 + 0], l0);
        atomicMaxF(&maxlog[dst * 2 + 1], l1);
    }
}

// ---------------- pass B: exp + segment sum ----------------
__global__ void k_passB(const int* __restrict__ ei, float* elog,
                        const float* __restrict__ maxlog, float* sum) {
    size_t i = (size_t)blockIdx.x * blockDim.x + threadIdx.x;
    if (i >= (size_t)NT * 2) return;
    int e = (int)(i >> 1), h = (int)(i & 1);
    int dst = (e < NE) ? ei[NE + e] : (e - NE);
    float w = expf(elog[i] - maxlog[dst * 2 + h]);
    elog[i] = w;
    atomicAdd(&sum[dst * 2 + h], w);
}

// ---------------- pass C: weighted aggregation, head-mean fused ----------------
template <int C>
__global__ void k_passC(const int* __restrict__ ei, const float* __restrict__ elog,
                        const float* __restrict__ sum, const float* __restrict__ xl,
                        float* agg) {
    int warp = (blockIdx.x * blockDim.x + threadIdx.x) >> 5;
    int lane = threadIdx.x & 31;
    if (warp >= NT) return;
    int src, dst;
    if (warp < NE) { src = ei[warp]; dst = ei[NE + warp]; }
    else           { src = dst = warp - NE; }
    float a = (lane < 2) ? elog[(size_t)warp * 2 + lane] / (sum[dst * 2 + lane] + 1e-16f) : 0.0f;
    float al0 = __shfl_sync(0xFFFFFFFFu, a, 0) * 0.5f;  // fold head mean (H=2)
    float al1 = __shfl_sync(0xFFFFFFFFu, a, 1) * 0.5f;
    const float* xls = xl + (size_t)src * 2 * C;
    #pragma unroll
    for (int j = 0; j < C / 32; j++) {
        int c = lane + j * 32;
        float v = al0 * xls[c] + al1 * xls[C + c];
        atomicAdd(&agg[(size_t)dst * C + c], v);
    }
}

// ---------------- batchnorm stats / apply + ELU ----------------
template <int C>
__global__ void k_bnstats(const float* __restrict__ agg, const float* __restrict__ bias,
                          double* bns) {
    int tid = blockIdx.x * blockDim.x + threadIdx.x;
    int total = gridDim.x * blockDim.x;
    int c = tid % C;
    int slot = tid / C;
    int tpc = total / C;
    float b = bias[c];
    float s = 0.0f, q = 0.0f;
    for (int n = slot; n < NN; n += tpc) {
        float v = agg[(size_t)n * C + c] + b;
        s += v;
        q += v * v;
    }
    atomicAdd(&bns[c], (double)s);
    atomicAdd(&bns[C + c], (double)q);
}

template <int C>
__global__ void k_bnapply(const float* __restrict__ agg, const float* __restrict__ bias,
                          const double* __restrict__ bns,
                          const float* __restrict__ g, const float* __restrict__ be,
                          float* out) {
    size_t i = (size_t)blockIdx.x * blockDim.x + threadIdx.x;
    if (i >= (size_t)NN * C) return;
    int c = (int)(i % C);
    double mu = bns[c] / (double)NN;
    double var = bns[C + c] / (double)NN - mu * mu;
    float y = (agg[i] + bias[c] - (float)mu) * rsqrtf((float)var + 1e-5f) * g[c] + be[c];
    out[i] = (y > 0.0f) ? y : expm1f(y);
}

// ---------------- global mean pool ----------------
__global__ void k_pool(const float* __restrict__ h, const int* __restrict__ batch,
                       float* pool, float* pcnt) {
    size_t i = (size_t)blockIdx.x * blockDim.x + threadIdx.x;
    if (i >= (size_t)NN * 64) return;
    int n = (int)(i >> 6), c = (int)(i & 63);
    int b = batch[n];
    atomicAdd(&pool[b * 64 + c], h[i]);
    if (c == 0) atomicAdd(&pcnt[b], 1.0f);
}

// ---------------- head ----------------
__global__ void k_head1(const float* __restrict__ pool, const float* __restrict__ pcnt,
                        const float* __restrict__ fc1w, const float* __restrict__ fc1b,
                        float* z, double* bns3) {
    __shared__ float sp[64];
    int g = blockIdx.x, t = threadIdx.x;
    float inv = 1.0f / fmaxf(pcnt[g], 1.0f);
    if (t < 64) sp[t] = pool[g * 64 + t] * inv;
    __syncthreads();
    if (t < 32) {
        float acc = fc1b[t];
        #pragma unroll
        for (int k = 0; k < 64; k++) acc += sp[k] * fc1w[k * 32 + t];
        z[g * 32 + t] = acc;
        atomicAdd(&bns3[t], (double)acc);
        atomicAdd(&bns3[32 + t], (double)(acc * acc));
    }
}

__global__ void k_head2(const float* __restrict__ z, const double* __restrict__ bns3,
                        const float* __restrict__ g3, const float* __restrict__ be3,
                        const float* __restrict__ fc2w, const float* __restrict__ fc2b,
                        float* out) {
    int warp = (blockIdx.x * blockDim.x + threadIdx.x) >> 5;
    int lane = threadIdx.x & 31;
    if (warp >= NG) return;
    double mu = bns3[lane] / (double)NG;
    double var = bns3[32 + lane] / (double)NG - mu * mu;
    float zl = z[warp * 32 + lane];
    float y = (zl - (float)mu) * rsqrtf((float)var + 1e-5f) * g3[lane] + be3[lane];
    y = (y > 0.0f) ? y : expm1f(y);
    float p = y * fc2w[lane];
    #pragma unroll
    for (int off = 16; off; off >>= 1) p += __shfl_xor_sync(0xFFFFFFFFu, p, off);
    if (lane == 0) out[warp] = 1.0f / (1.0f + expf(-(p + fc2b[0])));
}

// ---------------- launch ----------------
extern "C" void kernel_launch(void* const* d_in, const int* in_sizes, int n_in,
                              void* d_out, int out_size) {
    const float* x     = (const float*)d_in[0];
    const float* ea    = (const float*)d_in[1];
    const float* w1l   = (const float*)d_in[2];
    const float* b1l   = (const float*)d_in[3];
    const float* w1r   = (const float*)d_in[4];
    const float* b1r   = (const float*)d_in[5];
    const float* w1e   = (const float*)d_in[6];
    const float* att1  = (const float*)d_in[7];
    const float* bias1 = (const float*)d_in[8];
    const float* g1    = (const float*)d_in[9];
    const float* be1   = (const float*)d_in[10];
    const float* w2l   = (const float*)d_in[11];
    const float* b2l   = (const float*)d_in[12];
    const float* w2r   = (const float*)d_in[13];
    const float* b2r   = (const float*)d_in[14];
    const float* w2e   = (const float*)d_in[15];
    const float* att2  = (const float*)d_in[16];
    const float* bias2 = (const float*)d_in[17];
    const float* g2    = (const float*)d_in[18];
    const float* be2   = (const float*)d_in[19];
    const float* fc1w  = (const float*)d_in[20];
    const float* fc1b  = (const float*)d_in[21];
    const float* g3    = (const float*)d_in[22];
    const float* be3   = (const float*)d_in[23];
    const float* fc2w  = (const float*)d_in[24];
    const float* fc2b  = (const float*)d_in[25];
    const int*   ei    = (const int*)d_in[26];
    const int*   batch = (const int*)d_in[27];
    float* out = (float*)d_out;

    float *xl, *xr, *deg, *loop, *maxlog, *sumw, *ew, *agg, *hbuf, *pool, *pcnt, *zbuf;
    double *bns, *bns3;
    cudaGetSymbolAddress((void**)&xl, g_xl);
    cudaGetSymbolAddress((void**)&xr, g_xr);
    cudaGetSymbolAddress((void**)&deg, g_deg);
    cudaGetSymbolAddress((void**)&loop, g_loop);
    cudaGetSymbolAddress((void**)&maxlog, g_maxlog);
    cudaGetSymbolAddress((void**)&sumw, g_sum);
    cudaGetSymbolAddress((void**)&ew, g_w);
    cudaGetSymbolAddress((void**)&agg, g_agg);
    cudaGetSymbolAddress((void**)&hbuf, g_h);
    cudaGetSymbolAddress((void**)&pool, g_pool);
    cudaGetSymbolAddress((void**)&pcnt, g_pcnt);
    cudaGetSymbolAddress((void**)&zbuf, g_z);
    cudaGetSymbolAddress((void**)&bns, g_bns);
    cudaGetSymbolAddress((void**)&bns3, g_bns3);

    const int edgeWarpBlocks = (NT + 7) / 8;   // 8 warps (256 thr) per block

    // --- self-loop attrs ---
    cudaMemsetAsync(deg, 0, NN * sizeof(float));
    cudaMemsetAsync(loop, 0, NN * 3 * sizeof(float));
    k_deg<<<(NE + 255) / 256, 256>>>(ei, ea, deg, loop);
    k_loopfin<<<(NN + 255) / 256, 256>>>(loop, deg);

    // --- layer 1 ---
    k_lin<64, 64><<<4096, 128>>>(x, w1l, b1l, w1r, b1r, xl, xr);
    k_fill<<<(NN * 2 + 255) / 256, 256>>>(maxlog, -3.402823466e38f, NN * 2);
    cudaMemsetAsync(sumw, 0, NN * 2 * sizeof(float));
    cudaMemsetAsync(agg, 0, (size_t)NN * 32 * sizeof(float));
    k_passA<32><<<edgeWarpBlocks, 256>>>(ei, ea, loop, xl, xr, w1e, att1, ew, maxlog);
    k_passB<<<(int)(((size_t)NT * 2 + 255) / 256), 256>>>(ei, ew, maxlog, sumw);
    k_passC<32><<<edgeWarpBlocks, 256>>>(ei, ew, sumw, xl, agg);
    cudaMemsetAsync(bns, 0, 128 * sizeof(double));
    k_bnstats<32><<<128, 256>>>(agg, bias1, bns);
    k_bnapply<32><<<(int)(((size_t)NN * 32 + 255) / 256), 256>>>(agg, bias1, bns, g1, be1, hbuf);

    // --- layer 2 ---
    k_lin<32, 128><<<4096, 128>>>(hbuf, w2l, b2l, w2r, b2r, xl, xr);
    k_fill<<<(NN * 2 + 255) / 256, 256>>>(maxlog, -3.402823466e38f, NN * 2);
    cudaMemsetAsync(sumw, 0, NN * 2 * sizeof(float));
    cudaMemsetAsync(agg, 0, (size_t)NN * 64 * sizeof(float));
    k_passA<64><<<edgeWarpBlocks, 256>>>(ei, ea, loop, xl, xr, w2e, att2, ew, maxlog);
    k_passB<<<(int)(((size_t)NT * 2 + 255) / 256), 256>>>(ei, ew, maxlog, sumw);
    k_passC<64><<<edgeWarpBlocks, 256>>>(ei, ew, sumw, xl, agg);
    cudaMemsetAsync(bns, 0, 128 * sizeof(double));
    k_bnstats<64><<<128, 256>>>(agg, bias2, bns);
    k_bnapply<64><<<(int)(((size_t)NN * 64 + 255) / 256), 256>>>(agg, bias2, bns, g2, be2, hbuf);

    // --- pool + head ---
    cudaMemsetAsync(pool, 0, NG * 64 * sizeof(float));
    cudaMemsetAsync(pcnt, 0, NG * sizeof(float));
    k_pool<<<(int)(((size_t)NN * 64 + 255) / 256), 256>>>(hbuf, batch, pool, pcnt);
    cudaMemsetAsync(bns3, 0, 64 * sizeof(double));
    k_head1<<<NG, 64>>>(pool, pcnt, fc1w, fc1b, zbuf, bns3);
    k_head2<<<(NG * 32 + 255) / 256, 256>>>(zbuf, bns3, g3, be3, fc2w, fc2b, out);
}

// round 3
// speedup vs baseline: 1.7764x; 1.7764x over previous
#include <cuda_runtime.h>
#include <math.h>

#define NN 131072
#define NE 2097152
#define NG 512

// ---------------- scratch (device globals; no runtime allocation) ----------------
__device__ float  g_xl[NN * 128];
__device__ float  g_xr[NN * 128];
__device__ float  g_loop[NN * 3];
__device__ float  g_agg[NN * 64];
__device__ float  g_h[NN * 64];
__device__ float  g_pool[NG * 64];
__device__ float  g_pcnt[NG];
__device__ float  g_z[NG * 32];
__device__ double g_bns[128];
__device__ double g_bns3[64];
__device__ int    g_cnt[NN];
__device__ int    g_rowptr[NN];
__device__ int    g_cursor[NN];
__device__ int    g_srcs[NE];
__device__ float4 g_eas[NE];
__device__ int    g_bsum[128];

// ---------------- degree count + loop-attr sums ----------------
__global__ void k_count(const int* __restrict__ ei, const float* __restrict__ ea,
                        int* cnt, float* loop) {
    int e = blockIdx.x * blockDim.x + threadIdx.x;
    if (e >= NE) return;
    int dst = ei[NE + e];
    atomicAdd(&cnt[dst], 1);
    atomicAdd(&loop[dst * 3 + 0], ea[e * 3 + 0]);
    atomicAdd(&loop[dst * 3 + 1], ea[e * 3 + 1]);
    atomicAdd(&loop[dst * 3 + 2], ea[e * 3 + 2]);
}

__global__ void k_loopfin(float* loop, const int* __restrict__ cnt) {
    int n = blockIdx.x * blockDim.x + threadIdx.x;
    if (n >= NN) return;
    float inv = 1.0f / fmaxf((float)cnt[n], 1.0f);
    loop[n * 3 + 0] *= inv;
    loop[n * 3 + 1] *= inv;
    loop[n * 3 + 2] *= inv;
}

// ---------------- CSR scan (3-phase) ----------------
__global__ void k_scan1(const int* __restrict__ cnt, int* rowptr, int* bsum) {
    __shared__ int sh[1024];
    int t = threadIdx.x;
    int i = blockIdx.x * 1024 + t;
    int v = cnt[i];
    sh[t] = v;
    __syncthreads();
    for (int off = 1; off < 1024; off <<= 1) {
        int u = (t >= off) ? sh[t - off] : 0;
        __syncthreads();
        sh[t] += u;
        __syncthreads();
    }
    rowptr[i] = sh[t] - v;   // exclusive
    if (t == 1023) bsum[blockIdx.x] = sh[1023];
}

__global__ void k_scan2(int* bsum) {
    __shared__ int sh[128];
    int t = threadIdx.x;
    int orig = bsum[t];
    sh[t] = orig;
    __syncthreads();
    for (int off = 1; off < 128; off <<= 1) {
        int u = (t >= off) ? sh[t - off] : 0;
        __syncthreads();
        sh[t] += u;
        __syncthreads();
    }
    bsum[t] = sh[t] - orig;  // exclusive
}

__global__ void k_scan3(int* rowptr, const int* __restrict__ bsum, int* cursor) {
    int i = blockIdx.x * blockDim.x + threadIdx.x;
    if (i >= NN) return;
    int r = rowptr[i] + bsum[i >> 10];
    rowptr[i] = r;
    cursor[i] = r;
}

__global__ void k_scatter(const int* __restrict__ ei, const float* __restrict__ ea,
                          int* cursor, int* srcs, float4* eas) {
    int e = blockIdx.x * blockDim.x + threadIdx.x;
    if (e >= NE) return;
    int dst = ei[NE + e];
    int pos = atomicAdd(&cursor[dst], 1);
    srcs[pos] = ei[e];
    eas[pos] = make_float4(ea[e * 3 + 0], ea[e * 3 + 1], ea[e * 3 + 2], 0.0f);
}

// ---------------- node linear: xl = in@wl+bl, xr = in@wr+br ----------------
template <int INW, int OUTW>
__global__ void k_lin(const float* __restrict__ in,
                      const float* __restrict__ wl, const float* __restrict__ bl,
                      const float* __restrict__ wr, const float* __restrict__ br,
                      float* __restrict__ xl, float* __restrict__ xr) {
    __shared__ float sw[2 * INW * OUTW];
    __shared__ float sb[2 * OUTW];
    __shared__ float sx[INW];
    for (int i = threadIdx.x; i < INW * OUTW; i += blockDim.x) {
        sw[i] = wl[i];
        sw[INW * OUTW + i] = wr[i];
    }
    for (int i = threadIdx.x; i < OUTW; i += blockDim.x) {
        sb[i] = bl[i];
        sb[OUTW + i] = br[i];
    }
    __syncthreads();
    for (int n = blockIdx.x; n < NN; n += gridDim.x) {
        __syncthreads();
        for (int i = threadIdx.x; i < INW; i += blockDim.x) sx[i] = in[(size_t)n * INW + i];
        __syncthreads();
        for (int o = threadIdx.x; o < 2 * OUTW; o += blockDim.x) {
            int mat = (o < OUTW) ? 0 : 1;
            int c = mat ? (o - OUTW) : o;
            const float* w = &sw[mat * INW * OUTW];
            float acc = sb[mat * OUTW + c];
            #pragma unroll
            for (int k = 0; k < INW; k++) acc += sx[k] * w[k * OUTW + c];
            (mat ? xr : xl)[(size_t)n * OUTW + c] = acc;
        }
    }
}

// ---------------- fused GATv2: logits + online softmax + aggregation ----------------
// one warp per dst node; CSR edge list; self-loop appended in-loop
template <int C>
__global__ void k_gat(const int* __restrict__ rowptr, const int* __restrict__ cnt,
                      const int* __restrict__ srcs, const float4* __restrict__ eas,
                      const float* __restrict__ loop,
                      const float* __restrict__ xl, const float* __restrict__ xr,
                      const float* __restrict__ we, const float* __restrict__ att,
                      float* __restrict__ agg) {
    const int HC = 2 * C;
    const int J = HC / 32;
    int warp = (blockIdx.x * blockDim.x + threadIdx.x) >> 5;
    int lane = threadIdx.x & 31;
    if (warp >= NN) return;
    int beg = rowptr[warp];
    int d = cnt[warp];

    float rxr[J], w0[J], w1[J], w2[J], at[J], acc[J];
    #pragma unroll
    for (int j = 0; j < J; j++) {
        int col = lane + 32 * j;
        rxr[j] = xr[(size_t)warp * HC + col];
        w0[j] = we[col];
        w1[j] = we[HC + col];
        w2[j] = we[2 * HC + col];
        at[j] = att[col];
        acc[j] = 0.0f;
    }
    float m0 = -3.402823466e38f, m1 = -3.402823466e38f;
    float s0 = 0.0f, s1 = 0.0f;

    for (int i = 0; i <= d; i++) {
        int src;
        float a0, a1, a2;
        if (i < d) {
            src = srcs[beg + i];
            float4 a = eas[beg + i];
            a0 = a.x; a1 = a.y; a2 = a.z;
        } else {
            src = warp;
            a0 = loop[3 * warp + 0];
            a1 = loop[3 * warp + 1];
            a2 = loop[3 * warp + 2];
        }
        const float* xls = xl + (size_t)src * HC;
        float rxl[J];
        float l0 = 0.0f, l1 = 0.0f;
        #pragma unroll
        for (int j = 0; j < J; j++) {
            rxl[j] = xls[lane + 32 * j];
            float m = rxl[j] + rxr[j] + a0 * w0[j] + a1 * w1[j] + a2 * w2[j];
            m = (m > 0.0f) ? m : 0.2f * m;       // leaky_relu 0.2
            float cb = m * at[j];
            if (j < J / 2) l0 += cb; else l1 += cb;
        }
        #pragma unroll
        for (int off = 16; off; off >>= 1) {
            l0 += __shfl_xor_sync(0xFFFFFFFFu, l0, off);
            l1 += __shfl_xor_sync(0xFFFFFFFFu, l1, off);
        }
        float nm0 = fmaxf(m0, l0), nm1 = fmaxf(m1, l1);
        float sc0 = __expf(m0 - nm0), sc1 = __expf(m1 - nm1);
        float p0 = __expf(l0 - nm0), p1 = __expf(l1 - nm1);
        s0 = s0 * sc0 + p0;
        s1 = s1 * sc1 + p1;
        m0 = nm0; m1 = nm1;
        #pragma unroll
        for (int j = 0; j < J; j++) {
            float sc = (j < J / 2) ? sc0 : sc1;
            float p = (j < J / 2) ? p0 : p1;
            acc[j] = acc[j] * sc + p * rxl[j];
        }
    }
    float inv0 = 0.5f / (s0 + 1e-16f);
    float inv1 = 0.5f / (s1 + 1e-16f);
    #pragma unroll
    for (int j = 0; j < J / 2; j++)
        agg[(size_t)warp * C + lane + 32 * j] = acc[j] * inv0 + acc[j + J / 2] * inv1;
}

// ---------------- batchnorm stats / apply + ELU ----------------
template <int C>
__global__ void k_bnstats(const float* __restrict__ agg, const float* __restrict__ bias,
                          double* bns) {
    int tid = blockIdx.x * blockDim.x + threadIdx.x;
    int total = gridDim.x * blockDim.x;
    int c = tid % C;
    int slot = tid / C;
    int tpc = total / C;
    float b = bias[c];
    float s = 0.0f, q = 0.0f;
    for (int n = slot; n < NN; n += tpc) {
        float v = agg[(size_t)n * C + c] + b;
        s += v;
        q += v * v;
    }
    atomicAdd(&bns[c], (double)s);
    atomicAdd(&bns[C + c], (double)q);
}

template <int C>
__global__ void k_bnapply(const float* __restrict__ agg, const float* __restrict__ bias,
                          const double* __restrict__ bns,
                          const float* __restrict__ g, const float* __restrict__ be,
                          float* out) {
    size_t i = (size_t)blockIdx.x * blockDim.x + threadIdx.x;
    if (i >= (size_t)NN * C) return;
    int c = (int)(i % C);
    double mu = bns[c] / (double)NN;
    double var = bns[C + c] / (double)NN - mu * mu;
    float y = (agg[i] + bias[c] - (float)mu) * rsqrtf((float)var + 1e-5f) * g[c] + be[c];
    out[i] = (y > 0.0f) ? y : expm1f(y);
}

// layer-2 variant: BN+ELU fused directly into pool atomics (skips hbuf round trip)
__global__ void k_bnapply_pool(const float* __restrict__ agg, const float* __restrict__ bias,
                               const double* __restrict__ bns,
                               const float* __restrict__ g, const float* __restrict__ be,
                               const int* __restrict__ batch,
                               float* pool, float* pcnt) {
    size_t i = (size_t)blockIdx.x * blockDim.x + threadIdx.x;
    if (i >= (size_t)NN * 64) return;
    int c = (int)(i & 63);
    int n = (int)(i >> 6);
    double mu = bns[c] / (double)NN;
    double var = bns[64 + c] / (double)NN - mu * mu;
    float y = (agg[i] + bias[c] - (float)mu) * rsqrtf((float)var + 1e-5f) * g[c] + be[c];
    y = (y > 0.0f) ? y : expm1f(y);
    int b = batch[n];
    atomicAdd(&pool[b * 64 + c], y);
    if (c == 0) atomicAdd(&pcnt[b], 1.0f);
}

// ---------------- head ----------------
__global__ void k_head1(const float* __restrict__ pool, const float* __restrict__ pcnt,
                        const float* __restrict__ fc1w, const float* __restrict__ fc1b,
                        float* z, double* bns3) {
    __shared__ float sp[64];
    int g = blockIdx.x, t = threadIdx.x;
    float inv = 1.0f / fmaxf(pcnt[g], 1.0f);
    if (t < 64) sp[t] = pool[g * 64 + t] * inv;
    __syncthreads();
    if (t < 32) {
        float acc = fc1b[t];
        #pragma unroll
        for (int k = 0; k < 64; k++) acc += sp[k] * fc1w[k * 32 + t];
        z[g * 32 + t] = acc;
        atomicAdd(&bns3[t], (double)acc);
        atomicAdd(&bns3[32 + t], (double)(acc * acc));
    }
}

__global__ void k_head2(const float* __restrict__ z, const double* __restrict__ bns3,
                        const float* __restrict__ g3, const float* __restrict__ be3,
                        const float* __restrict__ fc2w, const float* __restrict__ fc2b,
                        float* out) {
    int warp = (blockIdx.x * blockDim.x + threadIdx.x) >> 5;
    int lane = threadIdx.x & 31;
    if (warp >= NG) return;
    double mu = bns3[lane] / (double)NG;
    double var = bns3[32 + lane] / (double)NG - mu * mu;
    float zl = z[warp * 32 + lane];
    float y = (zl - (float)mu) * rsqrtf((float)var + 1e-5f) * g3[lane] + be3[lane];
    y = (y > 0.0f) ? y : expm1f(y);
    float p = y * fc2w[lane];
    #pragma unroll
    for (int off = 16; off; off >>= 1) p += __shfl_xor_sync(0xFFFFFFFFu, p, off);
    if (lane == 0) out[warp] = 1.0f / (1.0f + expf(-(p + fc2b[0])));
}

// ---------------- launch ----------------
extern "C" void kernel_launch(void* const* d_in, const int* in_sizes, int n_in,
                              void* d_out, int out_size) {
    const float* x     = (const float*)d_in[0];
    const float* ea    = (const float*)d_in[1];
    const float* w1l   = (const float*)d_in[2];
    const float* b1l   = (const float*)d_in[3];
    const float* w1r   = (const float*)d_in[4];
    const float* b1r   = (const float*)d_in[5];
    const float* w1e   = (const float*)d_in[6];
    const float* att1  = (const float*)d_in[7];
    const float* bias1 = (const float*)d_in[8];
    const float* g1    = (const float*)d_in[9];
    const float* be1   = (const float*)d_in[10];
    const float* w2l   = (const float*)d_in[11];
    const float* b2l   = (const float*)d_in[12];
    const float* w2r   = (const float*)d_in[13];
    const float* b2r   = (const float*)d_in[14];
    const float* w2e   = (const float*)d_in[15];
    const float* att2  = (const float*)d_in[16];
    const float* bias2 = (const float*)d_in[17];
    const float* g2    = (const float*)d_in[18];
    const float* be2   = (const float*)d_in[19];
    const float* fc1w  = (const float*)d_in[20];
    const float* fc1b  = (const float*)d_in[21];
    const float* g3    = (const float*)d_in[22];
    const float* be3   = (const float*)d_in[23];
    const float* fc2w  = (const float*)d_in[24];
    const float* fc2b  = (const float*)d_in[25];
    const int*   ei    = (const int*)d_in[26];
    const int*   batch = (const int*)d_in[27];
    float* out = (float*)d_out;

    float *xl, *xr, *loop, *agg, *hbuf, *pool, *pcnt, *zbuf;
    double *bns, *bns3;
    int *cnt, *rowptr, *cursor, *srcs, *bsum;
    float4 *eas;
    cudaGetSymbolAddress((void**)&xl, g_xl);
    cudaGetSymbolAddress((void**)&xr, g_xr);
    cudaGetSymbolAddress((void**)&loop, g_loop);
    cudaGetSymbolAddress((void**)&agg, g_agg);
    cudaGetSymbolAddress((void**)&hbuf, g_h);
    cudaGetSymbolAddress((void**)&pool, g_pool);
    cudaGetSymbolAddress((void**)&pcnt, g_pcnt);
    cudaGetSymbolAddress((void**)&zbuf, g_z);
    cudaGetSymbolAddress((void**)&bns, g_bns);
    cudaGetSymbolAddress((void**)&bns3, g_bns3);
    cudaGetSymbolAddress((void**)&cnt, g_cnt);
    cudaGetSymbolAddress((void**)&rowptr, g_rowptr);
    cudaGetSymbolAddress((void**)&cursor, g_cursor);
    cudaGetSymbolAddress((void**)&srcs, g_srcs);
    cudaGetSymbolAddress((void**)&bsum, g_bsum);
    cudaGetSymbolAddress((void**)&eas, g_eas);

    const int gatBlocks = (NN * 32 + 255) / 256;  // warp per node

    // --- CSR build + self-loop attrs ---
    cudaMemsetAsync(cnt, 0, NN * sizeof(int));
    cudaMemsetAsync(loop, 0, NN * 3 * sizeof(float));
    k_count<<<(NE + 255) / 256, 256>>>(ei, ea, cnt, loop);
    k_loopfin<<<(NN + 255) / 256, 256>>>(loop, cnt);
    k_scan1<<<128, 1024>>>(cnt, rowptr, bsum);
    k_scan2<<<1, 128>>>(bsum);
    k_scan3<<<(NN + 255) / 256, 256>>>(rowptr, bsum, cursor);
    k_scatter<<<(NE + 255) / 256, 256>>>(ei, ea, cursor, srcs, eas);

    // --- layer 1 ---
    k_lin<64, 64><<<4096, 128>>>(x, w1l, b1l, w1r, b1r, xl, xr);
    k_gat<32><<<gatBlocks, 256>>>(rowptr, cnt, srcs, eas, loop, xl, xr, w1e, att1, agg);
    cudaMemsetAsync(bns, 0, 128 * sizeof(double));
    k_bnstats<32><<<128, 256>>>(agg, bias1, bns);
    k_bnapply<32><<<(int)(((size_t)NN * 32 + 255) / 256), 256>>>(agg, bias1, bns, g1, be1, hbuf);

    // --- layer 2 ---
    k_lin<32, 128><<<4096, 128>>>(hbuf, w2l, b2l, w2r, b2r, xl, xr);
    k_gat<64><<<gatBlocks, 256>>>(rowptr, cnt, srcs, eas, loop, xl, xr, w2e, att2, agg);
    cudaMemsetAsync(bns, 0, 128 * sizeof(double));
    k_bnstats<64><<<128, 256>>>(agg, bias2, bns);
    cudaMemsetAsync(pool, 0, NG * 64 * sizeof(float));
    cudaMemsetAsync(pcnt, 0, NG * sizeof(float));
    k_bnapply_pool<<<(int)(((size_t)NN * 64 + 255) / 256), 256>>>(agg, bias2, bns, g2, be2,
                                                                  batch, pool, pcnt);

    // --- head ---
    cudaMemsetAsync(bns3, 0, 64 * sizeof(double));
    k_head1<<<NG, 64>>>(pool, pcnt, fc1w, fc1b, zbuf, bns3);
    k_head2<<<(NG * 32 + 255) / 256, 256>>>(zbuf, bns3, g3, be3, fc2w, fc2b, out);
}

// round 5
// speedup vs baseline: 2.2789x; 1.2828x over previous
#include <cuda_runtime.h>
#include <math.h>

#define NN 131072
#define NE 2097152
#define NG 512

// ---------------- scratch (device globals; no runtime allocation) ----------------
__device__ float  g_xl[NN * 128];
__device__ float  g_xr[NN * 128];
__device__ float  g_agg[NN * 64];
__device__ float  g_pool[NG * 64];
__device__ float  g_pcnt[NG];
__device__ float  g_z[NG * 32];
__device__ double g_bns[128];
__device__ double g_bns3[64];
__device__ int    g_cnt[NN];
__device__ int    g_rowptr[NN];
__device__ int    g_cursor[NN];
__device__ float4 g_eas[NE];     // (a0,a1,a2, bitcast src)
__device__ int    g_bsum[128];

// ---------------- degree count ----------------
__global__ void k_count(const int* __restrict__ ei, int* cnt) {
    int e = blockIdx.x * blockDim.x + threadIdx.x;
    if (e >= NE) return;
    atomicAdd(&cnt[ei[NE + e]], 1);
}

// ---------------- CSR scan (3-phase) ----------------
__global__ void k_scan1(const int* __restrict__ cnt, int* rowptr, int* bsum) {
    __shared__ int sh[1024];
    int t = threadIdx.x;
    int i = blockIdx.x * 1024 + t;
    int v = cnt[i];
    sh[t] = v;
    __syncthreads();
    for (int off = 1; off < 1024; off <<= 1) {
        int u = (t >= off) ? sh[t - off] : 0;
        __syncthreads();
        sh[t] += u;
        __syncthreads();
    }
    rowptr[i] = sh[t] - v;   // exclusive
    if (t == 1023) bsum[blockIdx.x] = sh[1023];
}

__global__ void k_scan2(int* bsum) {
    __shared__ int sh[128];
    int t = threadIdx.x;
    int orig = bsum[t];
    sh[t] = orig;
    __syncthreads();
    for (int off = 1; off < 128; off <<= 1) {
        int u = (t >= off) ? sh[t - off] : 0;
        __syncthreads();
        sh[t] += u;
        __syncthreads();
    }
    bsum[t] = sh[t] - orig;  // exclusive
}

__global__ void k_scan3(int* rowptr, const int* __restrict__ bsum, int* cursor) {
    int i = blockIdx.x * blockDim.x + threadIdx.x;
    if (i >= NN) return;
    int r = rowptr[i] + bsum[i >> 10];
    rowptr[i] = r;
    cursor[i] = r;
}

__global__ void k_scatter(const int* __restrict__ ei, const float* __restrict__ ea,
                          int* cursor, float4* eas) {
    int e = blockIdx.x * blockDim.x + threadIdx.x;
    if (e >= NE) return;
    int dst = ei[NE + e];
    int pos = atomicAdd(&cursor[dst], 1);
    eas[pos] = make_float4(ea[e * 3 + 0], ea[e * 3 + 1], ea[e * 3 + 2],
                           __int_as_float(ei[e]));
}

// ---------------- register-tiled node linear ----------------
// grid (NN/64, 2): y=0 -> wl->xl, y=1 -> wr->xr. BM=64 nodes, BN cols, K inner.
// BNELU: apply batchnorm(+bias)+ELU to the input tile on load (layer-2 path).
template <int K, int BN, int TN, bool BNELU>
__global__ void k_lin(const float* __restrict__ in,
                      const float* __restrict__ wl, const float* __restrict__ bl,
                      const float* __restrict__ wr, const float* __restrict__ br,
                      const float* __restrict__ bias, const double* __restrict__ bns,
                      const float* __restrict__ gam, const float* __restrict__ bet,
                      float* __restrict__ xl, float* __restrict__ xr) {
    const int BM = 64, TM = 4;
    __shared__ float sx[BM][K + 1];
    __shared__ float sw[K * BN];
    __shared__ float ss[K], st[K];
    const float* w  = blockIdx.y ? wr : wl;
    const float* bb = blockIdx.y ? br : bl;
    float* out = blockIdx.y ? xr : xl;
    int tid = threadIdx.x;

    for (int i = tid; i < K * BN; i += 256) sw[i] = w[i];
    if (BNELU && tid < K) {
        double mu = bns[tid] / (double)NN;
        double var = bns[K + tid] / (double)NN - mu * mu;
        float rs = rsqrtf((float)var + 1e-5f);
        ss[tid] = rs * gam[tid];
        st[tid] = (bias[tid] - (float)mu) * rs * gam[tid] + bet[tid];
    }
    int node0 = blockIdx.x * BM;
    for (int i = tid; i < BM * K; i += 256) {
        int r = i / K, c = i % K;
        sx[r][c] = in[(size_t)(node0 + r) * K + c];
    }
    __syncthreads();
    if (BNELU) {
        for (int i = tid; i < BM * K; i += 256) {
            int r = i / K, c = i % K;
            float v = sx[r][c] * ss[c] + st[c];
            sx[r][c] = (v > 0.0f) ? v : expm1f(v);
        }
        __syncthreads();
    }

    int ty = tid / 16, tx = tid % 16;
    int nb = ty * TM, cb = tx * TN;
    float acc[TM][TN];
    #pragma unroll
    for (int m = 0; m < TM; m++)
        #pragma unroll
        for (int n = 0; n < TN; n++) acc[m][n] = bb[cb + n];

    #pragma unroll 4
    for (int k = 0; k < K; k++) {
        float a[TM], b[TN];
        #pragma unroll
        for (int m = 0; m < TM; m++) a[m] = sx[nb + m][k];
        #pragma unroll
        for (int n = 0; n < TN; n += 4) {
            float4 v = *(const float4*)&sw[k * BN + cb + n];
            b[n] = v.x; b[n + 1] = v.y; b[n + 2] = v.z; b[n + 3] = v.w;
        }
        #pragma unroll
        for (int m = 0; m < TM; m++)
            #pragma unroll
            for (int n = 0; n < TN; n++) acc[m][n] += a[m] * b[n];
    }
    #pragma unroll
    for (int m = 0; m < TM; m++)
        #pragma unroll
        for (int n = 0; n < TN; n += 4) {
            float4 v = make_float4(acc[m][n], acc[m][n + 1], acc[m][n + 2], acc[m][n + 3]);
            *(float4*)&out[(size_t)(node0 + nb + m) * BN + cb + n] = v;
        }
}

// ---------------- fused GATv2: logits + online softmax + aggregation ----------------
// one warp per dst node; self-loop attrs (mean of incident ea) computed in-loop
template <int C>
__global__ void k_gat(const int* __restrict__ rowptr, const int* __restrict__ cnt,
                      const float4* __restrict__ eas,
                      const float* __restrict__ xl, const float* __restrict__ xr,
                      const float* __restrict__ we, const float* __restrict__ att,
                      float* __restrict__ agg) {
    const int HC = 2 * C;
    const int J = HC / 32;
    int warp = (blockIdx.x * blockDim.x + threadIdx.x) >> 5;
    int lane = threadIdx.x & 31;
    if (warp >= NN) return;
    int beg = rowptr[warp];
    int d = cnt[warp];

    float rxr[J], w0[J], w1[J], w2[J], at[J], acc[J];
    #pragma unroll
    for (int j = 0; j < J; j++) {
        int col = lane + 32 * j;
        rxr[j] = xr[(size_t)warp * HC + col];
        w0[j] = we[col];
        w1[j] = we[HC + col];
        w2[j] = we[2 * HC + col];
        at[j] = att[col];
        acc[j] = 0.0f;
    }
    float m0 = -3.402823466e38f, m1 = -3.402823466e38f;
    float s0 = 0.0f, s1 = 0.0f;
    float as0 = 0.0f, as1 = 0.0f, as2 = 0.0f;

    for (int i = 0; i <= d; i++) {
        int src;
        float a0, a1, a2;
        if (i < d) {
            float4 a = eas[beg + i];
            a0 = a.x; a1 = a.y; a2 = a.z;
            src = __float_as_int(a.w);
            as0 += a0; as1 += a1; as2 += a2;
        } else {
            float inv = 1.0f / fmaxf((float)d, 1.0f);
            a0 = as0 * inv; a1 = as1 * inv; a2 = as2 * inv;
            src = warp;
        }
        const float* xls = xl + (size_t)src * HC;
        float rxl[J];
        float l0 = 0.0f, l1 = 0.0f;
        #pragma unroll
        for (int j = 0; j < J; j++) {
            rxl[j] = xls[lane + 32 * j];
            float m = rxl[j] + rxr[j] + a0 * w0[j] + a1 * w1[j] + a2 * w2[j];
            m = (m > 0.0f) ? m : 0.2f * m;       // leaky_relu 0.2
            float cb = m * at[j];
            if (j < J / 2) l0 += cb; else l1 += cb;
        }
        #pragma unroll
        for (int off = 16; off; off >>= 1) {
            l0 += __shfl_xor_sync(0xFFFFFFFFu, l0, off);
            l1 += __shfl_xor_sync(0xFFFFFFFFu, l1, off);
        }
        float nm0 = fmaxf(m0, l0), nm1 = fmaxf(m1, l1);
        float sc0 = __expf(m0 - nm0), sc1 = __expf(m1 - nm1);
        float p0 = __expf(l0 - nm0), p1 = __expf(l1 - nm1);
        s0 = s0 * sc0 + p0;
        s1 = s1 * sc1 + p1;
        m0 = nm0; m1 = nm1;
        #pragma unroll
        for (int j = 0; j < J; j++) {
            float sc = (j < J / 2) ? sc0 : sc1;
            float p = (j < J / 2) ? p0 : p1;
            acc[j] = acc[j] * sc + p * rxl[j];
        }
    }
    float inv0 = 0.5f / (s0 + 1e-16f);
    float inv1 = 0.5f / (s1 + 1e-16f);
    #pragma unroll
    for (int j = 0; j < J / 2; j++)
        agg[(size_t)warp * C + lane + 32 * j] = acc[j] * inv0 + acc[j + J / 2] * inv1;
}

// ---------------- batchnorm stats ----------------
template <int C>
__global__ void k_bnstats(const float* __restrict__ agg, const float* __restrict__ bias,
                          double* bns) {
    int tid = blockIdx.x * blockDim.x + threadIdx.x;
    int total = gridDim.x * blockDim.x;
    int c = tid % C;
    int slot = tid / C;
    int tpc = total / C;
    float b = bias[c];
    float s = 0.0f, q = 0.0f;
    for (int n = slot; n < NN; n += tpc) {
        float v = agg[(size_t)n * C + c] + b;
        s += v;
        q += v * v;
    }
    atomicAdd(&bns[c], (double)s);
    atomicAdd(&bns[C + c], (double)q);
}

// layer-2: BN+ELU fused directly into pool atomics
__global__ void k_bnapply_pool(const float* __restrict__ agg, const float* __restrict__ bias,
                               const double* __restrict__ bns,
                               const float* __restrict__ g, const float* __restrict__ be,
                               const int* __restrict__ batch,
                               float* pool, float* pcnt) {
    size_t i = (size_t)blockIdx.x * blockDim.x + threadIdx.x;
    if (i >= (size_t)NN * 64) return;
    int c = (int)(i & 63);
    int n = (int)(i >> 6);
    double mu = bns[c] / (double)NN;
    double var = bns[64 + c] / (double)NN - mu * mu;
    float y = (agg[i] + bias[c] - (float)mu) * rsqrtf((float)var + 1e-5f) * g[c] + be[c];
    y = (y > 0.0f) ? y : expm1f(y);
    int b = batch[n];
    atomicAdd(&pool[b * 64 + c], y);
    if (c == 0) atomicAdd(&pcnt[b], 1.0f);
}

// ---------------- head ----------------
__global__ void k_head1(const float* __restrict__ pool, const float* __restrict__ pcnt,
                        const float* __restrict__ fc1w, const float* __restrict__ fc1b,
                        float* z, double* bns3) {
    __shared__ float sp[64];
    int g = blockIdx.x, t = threadIdx.x;
    float inv = 1.0f / fmaxf(pcnt[g], 1.0f);
    if (t < 64) sp[t] = pool[g * 64 + t] * inv;
    __syncthreads();
    if (t < 32) {
        float acc = fc1b[t];
        #pragma unroll
        for (int k = 0; k < 64; k++) acc += sp[k] * fc1w[k * 32 + t];
        z[g * 32 + t] = acc;
        atomicAdd(&bns3[t], (double)acc);
        atomicAdd(&bns3[32 + t], (double)(acc * acc));
    }
}

__global__ void k_head2(const float* __restrict__ z, const double* __restrict__ bns3,
                        const float* __restrict__ g3, const float* __restrict__ be3,
                        const float* __restrict__ fc2w, const float* __restrict__ fc2b,
                        float* out) {
    int warp = (blockIdx.x * blockDim.x + threadIdx.x) >> 5;
    int lane = threadIdx.x & 31;
    if (warp >= NG) return;
    double mu = bns3[lane] / (double)NG;
    double var = bns3[32 + lane] / (double)NG - mu * mu;
    float zl = z[warp * 32 + lane];
    float y = (zl - (float)mu) * rsqrtf((float)var + 1e-5f) * g3[lane] + be3[lane];
    y = (y > 0.0f) ? y : expm1f(y);
    float p = y * fc2w[lane];
    #pragma unroll
    for (int off = 16; off; off >>= 1) p += __shfl_xor_sync(0xFFFFFFFFu, p, off);
    if (lane == 0) out[warp] = 1.0f / (1.0f + expf(-(p + fc2b[0])));
}

// ---------------- launch ----------------
extern "C" void kernel_launch(void* const* d_in, const int* in_sizes, int n_in,
                              void* d_out, int out_size) {
    const float* x     = (const float*)d_in[0];
    const float* ea    = (const float*)d_in[1];
    const float* w1l   = (const float*)d_in[2];
    const float* b1l   = (const float*)d_in[3];
    const float* w1r   = (const float*)d_in[4];
    const float* b1r   = (const float*)d_in[5];
    const float* w1e   = (const float*)d_in[6];
    const float* att1  = (const float*)d_in[7];
    const float* bias1 = (const float*)d_in[8];
    const float* g1    = (const float*)d_in[9];
    const float* be1   = (const float*)d_in[10];
    const float* w2l   = (const float*)d_in[11];
    const float* b2l   = (const float*)d_in[12];
    const float* w2r   = (const float*)d_in[13];
    const float* b2r   = (const float*)d_in[14];
    const float* w2e   = (const float*)d_in[15];
    const float* att2  = (const float*)d_in[16];
    const float* bias2 = (const float*)d_in[17];
    const float* g2    = (const float*)d_in[18];
    const float* be2   = (const float*)d_in[19];
    const float* fc1w  = (const float*)d_in[20];
    const float* fc1b  = (const float*)d_in[21];
    const float* g3    = (const float*)d_in[22];
    const float* be3   = (const float*)d_in[23];
    const float* fc2w  = (const float*)d_in[24];
    const float* fc2b  = (const float*)d_in[25];
    const int*   ei    = (const int*)d_in[26];
    const int*   batch = (const int*)d_in[27];
    float* out = (float*)d_out;

    float *xl, *xr, *agg, *pool, *pcnt, *zbuf;
    double *bns, *bns3;
    int *cnt, *rowptr, *cursor, *bsum;
    float4 *eas;
    cudaGetSymbolAddress((void**)&xl, g_xl);
    cudaGetSymbolAddress((void**)&xr, g_xr);
    cudaGetSymbolAddress((void**)&agg, g_agg);
    cudaGetSymbolAddress((void**)&pool, g_pool);
    cudaGetSymbolAddress((void**)&pcnt, g_pcnt);
    cudaGetSymbolAddress((void**)&zbuf, g_z);
    cudaGetSymbolAddress((void**)&bns, g_bns);
    cudaGetSymbolAddress((void**)&bns3, g_bns3);
    cudaGetSymbolAddress((void**)&cnt, g_cnt);
    cudaGetSymbolAddress((void**)&rowptr, g_rowptr);
    cudaGetSymbolAddress((void**)&cursor, g_cursor);
    cudaGetSymbolAddress((void**)&bsum, g_bsum);
    cudaGetSymbolAddress((void**)&eas, g_eas);

    const int gatBlocks = (NN * 32 + 255) / 256;  // warp per node
    dim3 linGrid(NN / 64, 2);

    // --- CSR build ---
    cudaMemsetAsync(cnt, 0, NN * sizeof(int));
    k_count<<<(NE + 255) / 256, 256>>>(ei, cnt);
    k_scan1<<<128, 1024>>>(cnt, rowptr, bsum);
    k_scan2<<<1, 128>>>(bsum);
    k_scan3<<<(NN + 255) / 256, 256>>>(rowptr, bsum, cursor);
    k_scatter<<<(NE + 255) / 256, 256>>>(ei, ea, cursor, eas);

    // --- layer 1 ---
    k_lin<64, 64, 4, false><<<linGrid, 256>>>(x, w1l, b1l, w1r, b1r,
                                              nullptr, nullptr, nullptr, nullptr, xl, xr);
    k_gat<32><<<gatBlocks, 256>>>(rowptr, cnt, eas, xl, xr, w1e, att1, agg);
    cudaMemsetAsync(bns, 0, 128 * sizeof(double));
    k_bnstats<32><<<128, 256>>>(agg, bias1, bns);

    // --- layer 2 (BN+ELU of layer-1 fused into the linear's input load) ---
    k_lin<32, 128, 8, true><<<linGrid, 256>>>(agg, w2l, b2l, w2r, b2r,
                                              bias1, bns, g1, be1, xl, xr);
    k_gat<64><<<gatBlocks, 256>>>(rowptr, cnt, eas, xl, xr, w2e, att2, agg);
    cudaMemsetAsync(bns, 0, 128 * sizeof(double));
    k_bnstats<64><<<128, 256>>>(agg, bias2, bns);

    // --- pool + head ---
    cudaMemsetAsync(pool, 0, NG * 64 * sizeof(float));
    cudaMemsetAsync(pcnt, 0, NG * sizeof(float));
    k_bnapply_pool<<<(int)(((size_t)NN * 64 + 255) / 256), 256>>>(agg, bias2, bns, g2, be2,
                                                                  batch, pool, pcnt);
    cudaMemsetAsync(bns3, 0, 64 * sizeof(double));
    k_head1<<<NG, 64>>>(pool, pcnt, fc1w, fc1b, zbuf, bns3);
    k_head2<<<(NG * 32 + 255) / 256, 256>>>(zbuf, bns3, g3, be3, fc2w, fc2b, out);
}

// round 6
// speedup vs baseline: 2.6076x; 1.1443x over previous
#include <cuda_runtime.h>
#include <math.h>

#define NN 131072
#define NE 2097152
#define NG 512

// ---------------- scratch (device globals; no runtime allocation) ----------------
__device__ float  g_xl[NN * 128];
__device__ float  g_xr[NN * 128];
__device__ float  g_agg[NN * 64];
__device__ float  g_pool[NG * 64];
__device__ float  g_z[NG * 32];
__device__ double g_bns[128];
__device__ double g_bns3[64];
__device__ int    g_cnt[NN];
__device__ int    g_rowptr[NN];
__device__ int    g_cursor[NN];
__device__ float4 g_eas[NE];     // (a0,a1,a2, bitcast src)
__device__ int    g_bsum[128];
__device__ int    g_gstart[NG + 1];

// ---------------- degree count ----------------
__global__ void k_count(const int* __restrict__ ei, int* cnt) {
    int e = blockIdx.x * blockDim.x + threadIdx.x;
    if (e >= NE) return;
    atomicAdd(&cnt[ei[NE + e]], 1);
}

// ---------------- CSR scan (3-phase) ----------------
__global__ void k_scan1(const int* __restrict__ cnt, int* rowptr, int* bsum) {
    __shared__ int sh[1024];
    int t = threadIdx.x;
    int i = blockIdx.x * 1024 + t;
    int v = cnt[i];
    sh[t] = v;
    __syncthreads();
    for (int off = 1; off < 1024; off <<= 1) {
        int u = (t >= off) ? sh[t - off] : 0;
        __syncthreads();
        sh[t] += u;
        __syncthreads();
    }
    rowptr[i] = sh[t] - v;   // exclusive
    if (t == 1023) bsum[blockIdx.x] = sh[1023];
}

__global__ void k_scan2(int* bsum) {
    __shared__ int sh[128];
    int t = threadIdx.x;
    int orig = bsum[t];
    sh[t] = orig;
    __syncthreads();
    for (int off = 1; off < 128; off <<= 1) {
        int u = (t >= off) ? sh[t - off] : 0;
        __syncthreads();
        sh[t] += u;
        __syncthreads();
    }
    bsum[t] = sh[t] - orig;  // exclusive
}

__global__ void k_scan3(int* rowptr, const int* __restrict__ bsum, int* cursor) {
    int i = blockIdx.x * blockDim.x + threadIdx.x;
    if (i >= NN) return;
    int r = rowptr[i] + bsum[i >> 10];
    rowptr[i] = r;
    cursor[i] = r;
}

__global__ void k_scatter(const int* __restrict__ ei, const float* __restrict__ ea,
                          int* cursor, float4* eas) {
    int e = blockIdx.x * blockDim.x + threadIdx.x;
    if (e >= NE) return;
    int dst = ei[NE + e];
    int pos = atomicAdd(&cursor[dst], 1);
    eas[pos] = make_float4(ea[e * 3 + 0], ea[e * 3 + 1], ea[e * 3 + 2],
                           __int_as_float(ei[e]));
}

// ---------------- graph boundaries (batch is sorted) ----------------
__global__ void k_bounds(const int* __restrict__ batch, int* gstart) {
    int g = blockIdx.x * blockDim.x + threadIdx.x;
    if (g > NG) return;
    int lo = 0, hi = NN;
    while (lo < hi) {
        int mid = (lo + hi) >> 1;
        if (batch[mid] < g) lo = mid + 1; else hi = mid;
    }
    gstart[g] = lo;
}

// ---------------- register-tiled node linear ----------------
template <int K, int BN, int TN, bool BNELU>
__global__ void k_lin(const float* __restrict__ in,
                      const float* __restrict__ wl, const float* __restrict__ bl,
                      const float* __restrict__ wr, const float* __restrict__ br,
                      const float* __restrict__ bias, const double* __restrict__ bns,
                      const float* __restrict__ gam, const float* __restrict__ bet,
                      float* __restrict__ xl, float* __restrict__ xr) {
    const int BM = 64, TM = 4;
    __shared__ float sx[BM][K + 1];
    __shared__ float sw[K * BN];
    __shared__ float ss[K], st[K];
    const float* w  = blockIdx.y ? wr : wl;
    const float* bb = blockIdx.y ? br : bl;
    float* out = blockIdx.y ? xr : xl;
    int tid = threadIdx.x;

    for (int i = tid; i < K * BN; i += 256) sw[i] = w[i];
    if (BNELU && tid < K) {
        double mu = bns[tid] / (double)NN;
        double var = bns[K + tid] / (double)NN - mu * mu;
        float rs = rsqrtf((float)var + 1e-5f);
        ss[tid] = rs * gam[tid];
        st[tid] = (bias[tid] - (float)mu) * rs * gam[tid] + bet[tid];
    }
    int node0 = blockIdx.x * BM;
    for (int i = tid; i < BM * K; i += 256) {
        int r = i / K, c = i % K;
        sx[r][c] = in[(size_t)(node0 + r) * K + c];
    }
    __syncthreads();
    if (BNELU) {
        for (int i = tid; i < BM * K; i += 256) {
            int r = i / K, c = i % K;
            float v = sx[r][c] * ss[c] + st[c];
            sx[r][c] = (v > 0.0f) ? v : expm1f(v);
        }
        __syncthreads();
    }

    int ty = tid / 16, tx = tid % 16;
    int nb = ty * TM, cb = tx * TN;
    float acc[TM][TN];
    #pragma unroll
    for (int m = 0; m < TM; m++)
        #pragma unroll
        for (int n = 0; n < TN; n++) acc[m][n] = bb[cb + n];

    #pragma unroll 4
    for (int k = 0; k < K; k++) {
        float a[TM], b[TN];
        #pragma unroll
        for (int m = 0; m < TM; m++) a[m] = sx[nb + m][k];
        #pragma unroll
        for (int n = 0; n < TN; n += 4) {
            float4 v = *(const float4*)&sw[k * BN + cb + n];
            b[n] = v.x; b[n + 1] = v.y; b[n + 2] = v.z; b[n + 3] = v.w;
        }
        #pragma unroll
        for (int m = 0; m < TM; m++)
            #pragma unroll
            for (int n = 0; n < TN; n++) acc[m][n] += a[m] * b[n];
    }
    #pragma unroll
    for (int m = 0; m < TM; m++)
        #pragma unroll
        for (int n = 0; n < TN; n += 4) {
            float4 v = make_float4(acc[m][n], acc[m][n + 1], acc[m][n + 2], acc[m][n + 3]);
            *(float4*)&out[(size_t)(node0 + nb + m) * BN + cb + n] = v;
        }
}

// ---------------- fused GATv2 (2-edge unrolled online softmax) ----------------
template <int J>
__device__ __forceinline__ void gat_one(const float* __restrict__ xls,
                                        float a0, float a1, float a2, int lane,
                                        const float* rxr, const float* w0,
                                        const float* w1, const float* w2,
                                        const float* at, float* acc,
                                        float& m0, float& m1, float& s0, float& s1) {
    float rxl[J];
    float l0 = 0.0f, l1 = 0.0f;
    #pragma unroll
    for (int j = 0; j < J; j++) {
        rxl[j] = xls[lane + 32 * j];
        float m = rxl[j] + rxr[j] + a0 * w0[j] + a1 * w1[j] + a2 * w2[j];
        m = (m > 0.0f) ? m : 0.2f * m;
        float cb = m * at[j];
        if (j < J / 2) l0 += cb; else l1 += cb;
    }
    #pragma unroll
    for (int off = 16; off; off >>= 1) {
        l0 += __shfl_xor_sync(0xFFFFFFFFu, l0, off);
        l1 += __shfl_xor_sync(0xFFFFFFFFu, l1, off);
    }
    float nm0 = fmaxf(m0, l0), nm1 = fmaxf(m1, l1);
    float sc0 = __expf(m0 - nm0), sc1 = __expf(m1 - nm1);
    float p0 = __expf(l0 - nm0), p1 = __expf(l1 - nm1);
    s0 = s0 * sc0 + p0;
    s1 = s1 * sc1 + p1;
    m0 = nm0; m1 = nm1;
    #pragma unroll
    for (int j = 0; j < J; j++) {
        float sc = (j < J / 2) ? sc0 : sc1;
        float p = (j < J / 2) ? p0 : p1;
        acc[j] = acc[j] * sc + p * rxl[j];
    }
}

template <int C>
__global__ void k_gat(const int* __restrict__ rowptr, const int* __restrict__ cnt,
                      const float4* __restrict__ eas,
                      const float* __restrict__ xl, const float* __restrict__ xr,
                      const float* __restrict__ we, const float* __restrict__ att,
                      float* __restrict__ agg) {
    const int HC = 2 * C;
    const int J = HC / 32;
    int warp = (blockIdx.x * blockDim.x + threadIdx.x) >> 5;
    int lane = threadIdx.x & 31;
    if (warp >= NN) return;
    int beg = rowptr[warp];
    int d = cnt[warp];

    float rxr[J], w0[J], w1[J], w2[J], at[J], acc[J];
    #pragma unroll
    for (int j = 0; j < J; j++) {
        int col = lane + 32 * j;
        rxr[j] = xr[(size_t)warp * HC + col];
        w0[j] = we[col];
        w1[j] = we[HC + col];
        w2[j] = we[2 * HC + col];
        at[j] = att[col];
        acc[j] = 0.0f;
    }
    float m0 = -3.402823466e38f, m1 = -3.402823466e38f;
    float s0 = 0.0f, s1 = 0.0f;
    float as0 = 0.0f, as1 = 0.0f, as2 = 0.0f;

    int i = 0;
    for (; i + 1 < d; i += 2) {
        float4 eA = eas[beg + i];
        float4 eB = eas[beg + i + 1];
        as0 += eA.x + eB.x; as1 += eA.y + eB.y; as2 += eA.z + eB.z;
        const float* xA = xl + (size_t)__float_as_int(eA.w) * HC;
        const float* xB = xl + (size_t)__float_as_int(eB.w) * HC;
        float rA[J], rB[J];
        float lA0 = 0.0f, lA1 = 0.0f, lB0 = 0.0f, lB1 = 0.0f;
        #pragma unroll
        for (int j = 0; j < J; j++) {
            int col = lane + 32 * j;
            rA[j] = xA[col];
            rB[j] = xB[col];
            float mA = rA[j] + rxr[j] + eA.x * w0[j] + eA.y * w1[j] + eA.z * w2[j];
            float mB = rB[j] + rxr[j] + eB.x * w0[j] + eB.y * w1[j] + eB.z * w2[j];
            mA = (mA > 0.0f) ? mA : 0.2f * mA;
            mB = (mB > 0.0f) ? mB : 0.2f * mB;
            float cA = mA * at[j], cB = mB * at[j];
            if (j < J / 2) { lA0 += cA; lB0 += cB; }
            else           { lA1 += cA; lB1 += cB; }
        }
        #pragma unroll
        for (int off = 16; off; off >>= 1) {
            lA0 += __shfl_xor_sync(0xFFFFFFFFu, lA0, off);
            lB0 += __shfl_xor_sync(0xFFFFFFFFu, lB0, off);
            lA1 += __shfl_xor_sync(0xFFFFFFFFu, lA1, off);
            lB1 += __shfl_xor_sync(0xFFFFFFFFu, lB1, off);
        }
        float nm0 = fmaxf(m0, fmaxf(lA0, lB0));
        float nm1 = fmaxf(m1, fmaxf(lA1, lB1));
        float sc0 = __expf(m0 - nm0), sc1 = __expf(m1 - nm1);
        float pA0 = __expf(lA0 - nm0), pB0 = __expf(lB0 - nm0);
        float pA1 = __expf(lA1 - nm1), pB1 = __expf(lB1 - nm1);
        s0 = s0 * sc0 + pA0 + pB0;
        s1 = s1 * sc1 + pA1 + pB1;
        m0 = nm0; m1 = nm1;
        #pragma unroll
        for (int j = 0; j < J; j++) {
            float sc = (j < J / 2) ? sc0 : sc1;
            float pA = (j < J / 2) ? pA0 : pA1;
            float pB = (j < J / 2) ? pB0 : pB1;
            acc[j] = acc[j] * sc + pA * rA[j] + pB * rB[j];
        }
    }
    if (i < d) {   // odd remainder
        float4 e = eas[beg + i];
        as0 += e.x; as1 += e.y; as2 += e.z;
        gat_one<J>(xl + (size_t)__float_as_int(e.w) * HC, e.x, e.y, e.z, lane,
                   rxr, w0, w1, w2, at, acc, m0, m1, s0, s1);
    }
    {   // self-loop with mean edge attrs
        float inv = 1.0f / fmaxf((float)d, 1.0f);
        gat_one<J>(xl + (size_t)warp * HC, as0 * inv, as1 * inv, as2 * inv, lane,
                   rxr, w0, w1, w2, at, acc, m0, m1, s0, s1);
    }
    float inv0 = 0.5f / (s0 + 1e-16f);
    float inv1 = 0.5f / (s1 + 1e-16f);
    #pragma unroll
    for (int j = 0; j < J / 2; j++)
        agg[(size_t)warp * C + lane + 32 * j] = acc[j] * inv0 + acc[j + J / 2] * inv1;
}

// ---------------- batchnorm stats ----------------
template <int C>
__global__ void k_bnstats(const float* __restrict__ agg, const float* __restrict__ bias,
                          double* bns) {
    int tid = blockIdx.x * blockDim.x + threadIdx.x;
    int total = gridDim.x * blockDim.x;
    int c = tid % C;
    int slot = tid / C;
    int tpc = total / C;
    float b = bias[c];
    float s = 0.0f, q = 0.0f;
    for (int n = slot; n < NN; n += tpc) {
        float v = agg[(size_t)n * C + c] + b;
        s += v;
        q += v * v;
    }
    atomicAdd(&bns[c], (double)s);
    atomicAdd(&bns[C + c], (double)q);
}

// ---------------- BN+ELU + mean pool, atomic-free (block per graph) ----------------
__global__ void k_pool(const float* __restrict__ agg, const float* __restrict__ bias,
                       const double* __restrict__ bns,
                       const float* __restrict__ g, const float* __restrict__ be,
                       const int* __restrict__ gstart, float* __restrict__ pool) {
    int gb = blockIdx.x;
    int c = threadIdx.x;   // 0..63
    int s = gstart[gb], e = gstart[gb + 1];
    double mu = bns[c] / (double)NN;
    double var = bns[64 + c] / (double)NN - mu * mu;
    float rs = rsqrtf((float)var + 1e-5f) * g[c];
    float sh = (bias[c] - (float)mu) * rs + be[c];
    float sum = 0.0f;
    for (int n = s; n < e; n++) {
        float y = agg[(size_t)n * 64 + c] * rs + sh;
        sum += (y > 0.0f) ? y : expm1f(y);
    }
    pool[gb * 64 + c] = sum / fmaxf((float)(e - s), 1.0f);
}

// ---------------- head ----------------
__global__ void k_head1(const float* __restrict__ pool,
                        const float* __restrict__ fc1w, const float* __restrict__ fc1b,
                        float* z, double* bns3) {
    __shared__ float sp[64];
    int g = blockIdx.x, t = threadIdx.x;
    if (t < 64) sp[t] = pool[g * 64 + t];
    __syncthreads();
    if (t < 32) {
        float acc = fc1b[t];
        #pragma unroll
        for (int k = 0; k < 64; k++) acc += sp[k] * fc1w[k * 32 + t];
        z[g * 32 + t] = acc;
        atomicAdd(&bns3[t], (double)acc);
        atomicAdd(&bns3[32 + t], (double)(acc * acc));
    }
}

__global__ void k_head2(const float* __restrict__ z, const double* __restrict__ bns3,
                        const float* __restrict__ g3, const float* __restrict__ be3,
                        const float* __restrict__ fc2w, const float* __restrict__ fc2b,
                        float* out) {
    int warp = (blockIdx.x * blockDim.x + threadIdx.x) >> 5;
    int lane = threadIdx.x & 31;
    if (warp >= NG) return;
    double mu = bns3[lane] / (double)NG;
    double var = bns3[32 + lane] / (double)NG - mu * mu;
    float zl = z[warp * 32 + lane];
    float y = (zl - (float)mu) * rsqrtf((float)var + 1e-5f) * g3[lane] + be3[lane];
    y = (y > 0.0f) ? y : expm1f(y);
    float p = y * fc2w[lane];
    #pragma unroll
    for (int off = 16; off; off >>= 1) p += __shfl_xor_sync(0xFFFFFFFFu, p, off);
    if (lane == 0) out[warp] = 1.0f / (1.0f + expf(-(p + fc2b[0])));
}

// ---------------- launch ----------------
extern "C" void kernel_launch(void* const* d_in, const int* in_sizes, int n_in,
                              void* d_out, int out_size) {
    const float* x     = (const float*)d_in[0];
    const float* ea    = (const float*)d_in[1];
    const float* w1l   = (const float*)d_in[2];
    const float* b1l   = (const float*)d_in[3];
    const float* w1r   = (const float*)d_in[4];
    const float* b1r   = (const float*)d_in[5];
    const float* w1e   = (const float*)d_in[6];
    const float* att1  = (const float*)d_in[7];
    const float* bias1 = (const float*)d_in[8];
    const float* g1    = (const float*)d_in[9];
    const float* be1   = (const float*)d_in[10];
    const float* w2l   = (const float*)d_in[11];
    const float* b2l   = (const float*)d_in[12];
    const float* w2r   = (const float*)d_in[13];
    const float* b2r   = (const float*)d_in[14];
    const float* w2e   = (const float*)d_in[15];
    const float* att2  = (const float*)d_in[16];
    const float* bias2 = (const float*)d_in[17];
    const float* g2    = (const float*)d_in[18];
    const float* be2   = (const float*)d_in[19];
    const float* fc1w  = (const float*)d_in[20];
    const float* fc1b  = (const float*)d_in[21];
    const float* g3    = (const float*)d_in[22];
    const float* be3   = (const float*)d_in[23];
    const float* fc2w  = (const float*)d_in[24];
    const float* fc2b  = (const float*)d_in[25];
    const int*   ei    = (const int*)d_in[26];
    const int*   batch = (const int*)d_in[27];
    float* out = (float*)d_out;

    float *xl, *xr, *agg, *pool, *zbuf;
    double *bns, *bns3;
    int *cnt, *rowptr, *cursor, *bsum, *gstart;
    float4 *eas;
    cudaGetSymbolAddress((void**)&xl, g_xl);
    cudaGetSymbolAddress((void**)&xr, g_xr);
    cudaGetSymbolAddress((void**)&agg, g_agg);
    cudaGetSymbolAddress((void**)&pool, g_pool);
    cudaGetSymbolAddress((void**)&zbuf, g_z);
    cudaGetSymbolAddress((void**)&bns, g_bns);
    cudaGetSymbolAddress((void**)&bns3, g_bns3);
    cudaGetSymbolAddress((void**)&cnt, g_cnt);
    cudaGetSymbolAddress((void**)&rowptr, g_rowptr);
    cudaGetSymbolAddress((void**)&cursor, g_cursor);
    cudaGetSymbolAddress((void**)&bsum, g_bsum);
    cudaGetSymbolAddress((void**)&eas, g_eas);
    cudaGetSymbolAddress((void**)&gstart, g_gstart);

    const int gatBlocks = (NN * 32 + 255) / 256;  // warp per node
    dim3 linGrid(NN / 64, 2);

    // --- CSR build + graph bounds ---
    cudaMemsetAsync(cnt, 0, NN * sizeof(int));
    k_count<<<(NE + 255) / 256, 256>>>(ei, cnt);
    k_scan1<<<128, 1024>>>(cnt, rowptr, bsum);
    k_scan2<<<1, 128>>>(bsum);
    k_scan3<<<(NN + 255) / 256, 256>>>(rowptr, bsum, cursor);
    k_scatter<<<(NE + 255) / 256, 256>>>(ei, ea, cursor, eas);
    k_bounds<<<3, 256>>>(batch, gstart);

    // --- layer 1 ---
    k_lin<64, 64, 4, false><<<linGrid, 256>>>(x, w1l, b1l, w1r, b1r,
                                              nullptr, nullptr, nullptr, nullptr, xl, xr);
    k_gat<32><<<gatBlocks, 256>>>(rowptr, cnt, eas, xl, xr, w1e, att1, agg);
    cudaMemsetAsync(bns, 0, 128 * sizeof(double));
    k_bnstats<32><<<128, 256>>>(agg, bias1, bns);

    // --- layer 2 (BN+ELU of layer-1 fused into the linear's input load) ---
    k_lin<32, 128, 8, true><<<linGrid, 256>>>(agg, w2l, b2l, w2r, b2r,
                                              bias1, bns, g1, be1, xl, xr);
    k_gat<64><<<gatBlocks, 256>>>(rowptr, cnt, eas, xl, xr, w2e, att2, agg);
    cudaMemsetAsync(bns, 0, 128 * sizeof(double));
    k_bnstats<64><<<128, 256>>>(agg, bias2, bns);

    // --- pool + head (atomic-free) ---
    k_pool<<<NG, 64>>>(agg, bias2, bns, g2, be2, gstart, pool);
    cudaMemsetAsync(bns3, 0, 64 * sizeof(double));
    k_head1<<<NG, 64>>>(pool, fc1w, fc1b, zbuf, bns3);
    k_head2<<<(NG * 32 + 255) / 256, 256>>>(zbuf, bns3, g3, be3, fc2w, fc2b, out);
}